// round 1
// baseline (speedup 1.0000x reference)
#include <cuda_runtime.h>
#include <cuda_bf16.h>

#define EDGE_R 4864
#define FEAT   144
#define YDIM   25
#define NPATH  19
#define CYTOT  259
#define GTOT   1104

// Path tables (lo,li,lf enumeration order matches the reference loops).
__constant__ int c_lo[NPATH]    = {0,0,0,1,1,1,1,1,1,1,2,2,2,2,2,2,2,2,2};
__constant__ int c_li[NPATH]    = {0,1,2,0,1,1,1,2,2,2,0,1,1,1,2,2,2,2,2};
__constant__ int c_lf[NPATH]    = {0,1,2,1,0,1,2,1,2,3,2,1,2,3,0,1,2,3,4};
// r_pair_offset + k  (element offset of R[0,0] for this path within the rbf row)
__constant__ int c_rbase[NPATH] = {0,256,512,768,1024,1025,1026,1792,1793,1794,
                                   2560,2816,2817,2818,3584,3585,3586,3587,3588};
__constant__ int c_nlf[NPATH]   = {1,1,1,1,3,3,3,3,3,3,1,3,3,3,5,5,5,5,5};
__constant__ int c_cgoff[NPATH] = {0,1,10,35,44,53,80,125,170,245,350,375,420,495,600,625,700,825,1000};
__constant__ int c_goff[NPATH]  = {0,16,32,48,96,144,192,240,288,336,384,464,544,624,704,784,864,944,1024};
__constant__ int c_cyoff[NPATH] = {0,1,4,9,12,21,30,39,54,69,84,89,104,119,134,159,184,209,234};
__constant__ int c_finoff[3]    = {0,16,64};
__constant__ int c_outoff[3]    = {0,16,64};

__global__ void zero_kernel(float* out, int n) {
    int i = blockIdx.x * blockDim.x + threadIdx.x;
    if (i < n) out[i] = 0.f;
}

// Heavy contraction for one (u-quad, path) slot: acc[4][DO] += R[u,v] * G[v,o]
template<int DO>
__device__ __forceinline__ void do_path(int q, float w,
                                        const float* __restrict__ sR, int rbase, int nlf,
                                        const float* __restrict__ sG, int goff,
                                        float* __restrict__ sB, int ooff)
{
    float acc[4][DO];
    #pragma unroll
    for (int uu = 0; uu < 4; ++uu)
        #pragma unroll
        for (int o = 0; o < DO; ++o) acc[uu][o] = 0.f;

    const int u0 = q * 4;
    #pragma unroll
    for (int v = 0; v < 16; ++v) {
        float g[DO];
        #pragma unroll
        for (int o = 0; o < DO; ++o) g[o] = sG[goff + v * DO + o];
        #pragma unroll
        for (int uu = 0; uu < 4; ++uu) {
            float r = sR[rbase + ((u0 + uu) * 16 + v) * nlf];
            #pragma unroll
            for (int o = 0; o < DO; ++o) acc[uu][o] = fmaf(r, g[o], acc[uu][o]);
        }
    }
    #pragma unroll
    for (int uu = 0; uu < 4; ++uu)
        #pragma unroll
        for (int o = 0; o < DO; ++o)
            atomicAdd(&sB[ooff + (u0 + uu) * DO + o], w * acc[uu][o]);
}

__global__ void __launch_bounds__(128)
tp_kernel(const float* __restrict__ feat, const float* __restrict__ rbf,
          const float* __restrict__ Y,    const float* __restrict__ cg,
          const float* __restrict__ W,    const int* __restrict__ aidx,
          const int* __restrict__ bidx,   float* __restrict__ out, int E)
{
    __shared__ float sR[EDGE_R];
    __shared__ float sF[FEAT];
    __shared__ float sY[YDIM];
    __shared__ float sCY[CYTOT];
    __shared__ float sG[GTOT];
    __shared__ float sB[FEAT];

    const int e   = blockIdx.x;
    const int tid = threadIdx.x;
    if (e >= E) return;

    const int a = aidx[e];
    const int b = bidx[e];

    // ---- Phase A: stage inputs (coalesced float4 for the big rbf row) ----
    {
        const float4* r4 = reinterpret_cast<const float4*>(rbf + (size_t)e * EDGE_R);
        float4* s4 = reinterpret_cast<float4*>(sR);
        #pragma unroll
        for (int i = 0; i < 9; ++i) s4[tid + i * 128] = r4[tid + i * 128];
        if (tid < 64) s4[tid + 1152] = r4[tid + 1152];      // 1216 float4 total

        if (tid < 36)
            reinterpret_cast<float4*>(sF)[tid] =
                reinterpret_cast<const float4*>(feat + (size_t)b * FEAT)[tid];
        if (tid >= 64 && tid < 64 + YDIM)
            sY[tid - 64] = Y[(size_t)e * YDIM + (tid - 64)];

        sB[tid] = 0.f;
        if (tid < FEAT - 128) sB[128 + tid] = 0.f;
    }
    __syncthreads();

    // ---- Phase B1: CY[o,i] = sum_f cg[o,i,f] * Y[lf^2 + f]  (259 elems) ----
    #pragma unroll
    for (int p = 0; p < NPATH; ++p) {
        const int lo = c_lo[p], li = c_li[p], lf = c_lf[p];
        const int doo = 2 * lo + 1, di = 2 * li + 1, df = 2 * lf + 1;
        const int n = doo * di;
        if (tid < n) {
            const int cgb = c_cgoff[p] + tid * df;
            const int yb  = lf * lf;
            float s = 0.f;
            for (int f = 0; f < df; ++f)
                s = fmaf(__ldg(&cg[cgb + f]), sY[yb + f], s);
            sCY[c_cyoff[p] + tid] = s;                // layout [o*di + i]
        }
    }
    __syncthreads();

    // ---- Phase B2: G[v,o] = sum_i CY[o,i] * F[v,i]  (1104 elems) ----
    #pragma unroll
    for (int p = 0; p < NPATH; ++p) {
        const int lo = c_lo[p], li = c_li[p];
        const int doo = 2 * lo + 1, di = 2 * li + 1;
        const int n = 16 * doo;
        if (tid < n) {
            const int v = tid / doo, o = tid - v * doo;
            const float* cy = &sCY[c_cyoff[p] + o * di];
            const float* fv = &sF[c_finoff[li] + v * di];
            float s = 0.f;
            for (int i2 = 0; i2 < di; ++i2) s = fmaf(cy[i2], fv[i2], s);
            sG[c_goff[p] + v * doo + o] = s;
        }
    }
    __syncthreads();

    // ---- Phase C: B[u,o] += W_p * sum_v R_p[u,v] * G_p[v,o] ----
    // slot = (u-quad q = tid&3, path p = tid>>2); 76 active threads.
    {
        const int p = tid >> 2, q = tid & 3;
        if (p < NPATH) {
            const int lo = c_lo[p];
            const float w = __ldg(&W[p]);
            const int rbase = c_rbase[p], nlf = c_nlf[p];
            const int goff = c_goff[p], ooff = c_outoff[lo];
            if (lo == 0)      do_path<1>(q, w, sR, rbase, nlf, sG, goff, sB, ooff);
            else if (lo == 1) do_path<3>(q, w, sR, rbase, nlf, sG, goff, sB, ooff);
            else              do_path<5>(q, w, sR, rbase, nlf, sG, goff, sB, ooff);
        }
    }
    __syncthreads();

    // ---- Phase D: scatter-add into destination node ----
    {
        float* dst = out + (size_t)a * FEAT;
        atomicAdd(&dst[tid], sB[tid]);
        if (tid < FEAT - 128) atomicAdd(&dst[128 + tid], sB[128 + tid]);
    }
}

extern "C" void kernel_launch(void* const* d_in, const int* in_sizes, int n_in,
                              void* d_out, int out_size)
{
    const float* feat = (const float*)d_in[0];
    const float* rbf  = (const float*)d_in[1];
    const float* Y    = (const float*)d_in[2];
    const float* cg   = (const float*)d_in[3];
    const float* W    = (const float*)d_in[4];
    const int*   a    = (const int*)d_in[5];
    const int*   b    = (const int*)d_in[6];
    float* out = (float*)d_out;

    const int E = in_sizes[1] / EDGE_R;

    zero_kernel<<<(out_size + 255) / 256, 256>>>(out, out_size);
    tp_kernel<<<E, 128>>>(feat, rbf, Y, cg, W, a, b, out, E);
}

// round 2
// speedup vs baseline: 1.4063x; 1.4063x over previous
#include <cuda_runtime.h>
#include <cuda_bf16.h>

#define NT     160
#define FEAT   144
#define YDIM   25
#define EDGE_R 4864
#define NPATH  19

// Per-path tables (enumeration order = reference loops)
__constant__ int c_lo[NPATH]    = {0,0,0,1,1,1,1,1,1,1,2,2,2,2,2,2,2,2,2};
__constant__ int c_li[NPATH]    = {0,1,2,0,1,1,1,2,2,2,0,1,1,1,2,2,2,2,2};
__constant__ int c_lf[NPATH]    = {0,1,2,1,0,1,2,1,2,3,2,1,2,3,0,1,2,3,4};
__constant__ int c_cgoff[NPATH] = {0,1,10,35,44,53,80,125,170,245,350,375,420,495,600,625,700,825,1000};
__constant__ int c_cyoff[NPATH] = {0,1,4,9,12,21,30,39,54,69,84,89,104,119,134,159,184,209,234};
__constant__ int c_pair[NPATH]  = {0,1,2,3,4,4,4,5,5,5,6,7,7,7,8,8,8,8,8};
__constant__ int c_k[NPATH]     = {0,0,0,0,0,1,2,0,1,2,0,0,1,2,0,1,2,3,4};
// Per (lo,li) pair tables: padded G'' word base, nlf
__constant__ int c_gw[9]   = {0,20,40,60,120,276,432,532,792};
__constant__ int c_nlf9[9] = {1,1,1,1,3,3,1,3,5};
__constant__ int c_finoff[3] = {0,16,64};

__global__ void zero_kernel(float* out, int n) {
    int i = blockIdx.x * blockDim.x + threadIdx.x;
    if (i < n) out[i] = 0.f;
}

// Map global float4 index within the rbf row -> padded smem float4 index.
// Padded layout per pair: 16 u-rows of (4*nlf+1) float4 (word stride 16nlf+4 == 20 mod 32).
__device__ __forceinline__ int map_r(int G4) {
    if (G4 < 256) {               // pairs 0-3, nlf=1, 64 f4 each, dst bases 0,80,160,240
        int r = G4 >> 6, local = G4 & 63;
        return r * 80 + (local >> 2) * 5 + (local & 3);
    } else if (G4 < 448) {        // pair 4, nlf=3
        int local = G4 - 256; int u = local / 12, rem = local - u * 12;
        return 320 + u * 13 + rem;
    } else if (G4 < 640) {        // pair 5, nlf=3
        int local = G4 - 448; int u = local / 12, rem = local - u * 12;
        return 528 + u * 13 + rem;
    } else if (G4 < 704) {        // pair 6, nlf=1
        int local = G4 - 640;
        return 736 + (local >> 2) * 5 + (local & 3);
    } else if (G4 < 896) {        // pair 7, nlf=3
        int local = G4 - 704; int u = local / 12, rem = local - u * 12;
        return 816 + u * 13 + rem;
    } else {                      // pair 8, nlf=5
        int local = G4 - 896; int u = local / 20, rem = local - u * 20;
        return 1024 + u * 21 + rem;
    }
}

// acc += sum_j R4[row+j] . G4[row'+j]  over 4*NLF float4 (= 16*NLF words, v*nlf+k interleaved)
template<int NLF>
__device__ __forceinline__ float pairdot(const float4* __restrict__ sR4,
                                         const float4* __restrict__ sG4,
                                         int rf4, int gf4, int u, int o) {
    const float4* r = sR4 + rf4 + u * (4 * NLF + 1);
    const float4* g = sG4 + gf4 + o * (4 * NLF + 1);
    float acc = 0.f;
    #pragma unroll
    for (int j = 0; j < 4 * NLF; ++j) {
        float4 a = r[j];
        float4 b = g[j];
        acc = fmaf(a.x, b.x, acc);
        acc = fmaf(a.y, b.y, acc);
        acc = fmaf(a.z, b.z, acc);
        acc = fmaf(a.w, b.w, acc);
    }
    return acc;
}

__global__ void __launch_bounds__(NT, 7)
tp_kernel(const float* __restrict__ feat, const float* __restrict__ rbf,
          const float* __restrict__ Y,    const float* __restrict__ cg,
          const float* __restrict__ W,    const int* __restrict__ aidx,
          const int* __restrict__ bidx,   float* __restrict__ out, int E)
{
    __shared__ float4 sR4[1360];   // padded R, 5440 words
    __shared__ float4 sG4[303];    // padded/interleaved W*G, 1212 words
    __shared__ float  sF[FEAT];
    __shared__ float  sY[YDIM];
    __shared__ float  sCY[259];

    const int e   = blockIdx.x;
    const int tid = threadIdx.x;
    if (e >= E) return;

    const int a = aidx[e];
    const int b = bidx[e];

    // ---- Phase A: stage R (coalesced LDG.128 -> padded STS.128), F, Y ----
    {
        const float4* r4 = reinterpret_cast<const float4*>(rbf + (size_t)e * EDGE_R);
        #pragma unroll
        for (int i = 0; i < 8; ++i) {
            int G4 = tid + i * NT;
            if (G4 < 1216) sR4[map_r(G4)] = r4[G4];
        }
        if (tid < 36)
            reinterpret_cast<float4*>(sF)[tid] =
                reinterpret_cast<const float4*>(feat + (size_t)b * FEAT)[tid];
        if (tid >= 64 && tid < 64 + YDIM)
            sY[tid - 64] = Y[(size_t)e * YDIM + (tid - 64)];
    }
    __syncthreads();

    // ---- Phase B1: CY[o,i] = sum_f cg[o,i,f] * Y[lf^2+f] ----
    #pragma unroll
    for (int p = 0; p < NPATH; ++p) {
        const int lo = c_lo[p], li = c_li[p], lf = c_lf[p];
        const int doo = 2 * lo + 1, di = 2 * li + 1, df = 2 * lf + 1;
        if (tid < doo * di) {
            const int cgb = c_cgoff[p] + tid * df;
            const int yb  = lf * lf;
            float s = 0.f;
            for (int f = 0; f < df; ++f)
                s = fmaf(__ldg(&cg[cgb + f]), sY[yb + f], s);
            sCY[c_cyoff[p] + tid] = s;
        }
    }
    __syncthreads();

    // ---- Phase B2: G''[pair][o][v*nlf+k] = W_p * sum_i CY[o,i]*F[v,i] (interleaved+padded) ----
    float* sG = reinterpret_cast<float*>(sG4);
    #pragma unroll
    for (int p = 0; p < NPATH; ++p) {
        const int lo = c_lo[p], li = c_li[p];
        const int doo = 2 * lo + 1, di = 2 * li + 1;
        const int n = 16 * doo;
        if (tid < n) {
            const int v = tid / doo, o = tid - v * doo;
            const float* cy = &sCY[c_cyoff[p] + o * di];
            const float* fv = &sF[c_finoff[li] + v * di];
            float s = 0.f;
            for (int i2 = 0; i2 < di; ++i2) s = fmaf(cy[i2], fv[i2], s);
            const int pr  = c_pair[p];
            const int nlf = c_nlf9[pr];
            sG[c_gw[pr] + o * (16 * nlf + 4) + v * nlf + c_k[p]] = __ldg(&W[p]) * s;
        }
    }
    __syncthreads();

    // ---- Phase C: one thread per output element; register accumulator ----
    if (tid < FEAT) {
        float acc;
        int outi;
        if (tid < 16) {                       // lo=0: u=tid, o=0
            const int u = tid;
            acc  = pairdot<1>(sR4, sG4,    0,   0, u, 0);
            acc += pairdot<1>(sR4, sG4,   80,   5, u, 0);
            acc += pairdot<1>(sR4, sG4,  160,  10, u, 0);
            outi = u;
        } else if (tid < 64) {                // lo=1
            const int s = tid - 16, u = s / 3, o = s - u * 3;
            acc  = pairdot<1>(sR4, sG4,  240,  15, u, o);
            acc += pairdot<3>(sR4, sG4,  320,  30, u, o);
            acc += pairdot<3>(sR4, sG4,  528,  69, u, o);
            outi = 16 + u * 3 + o;
        } else {                              // lo=2
            const int s = tid - 64, u = s / 5, o = s - u * 5;
            acc  = pairdot<1>(sR4, sG4,  736, 108, u, o);
            acc += pairdot<3>(sR4, sG4,  816, 133, u, o);
            acc += pairdot<5>(sR4, sG4, 1024, 198, u, o);
            outi = 64 + u * 5 + o;
        }
        atomicAdd(out + (size_t)a * FEAT + outi, acc);
    }
}

extern "C" void kernel_launch(void* const* d_in, const int* in_sizes, int n_in,
                              void* d_out, int out_size)
{
    const float* feat = (const float*)d_in[0];
    const float* rbf  = (const float*)d_in[1];
    const float* Y    = (const float*)d_in[2];
    const float* cg   = (const float*)d_in[3];
    const float* W    = (const float*)d_in[4];
    const int*   a    = (const int*)d_in[5];
    const int*   b    = (const int*)d_in[6];
    float* out = (float*)d_out;

    const int E = in_sizes[1] / EDGE_R;

    zero_kernel<<<(out_size + 255) / 256, 256>>>(out, out_size);
    tp_kernel<<<E, NT>>>(feat, rbf, Y, cg, W, a, b, out, E);
}